// round 10
// baseline (speedup 1.0000x reference)
#include <cuda_runtime.h>
#include <math.h>

#define NQ 4
#define DIM 16
#define NB 4
#define SS 512
#define EE 512
#define NTOK (NB*SS)           // 2048
#define OUT_ELEMS (NB*SS*EE)   // 1048576

// ---------------- scratch (no device allocation allowed) ----------------
__device__ float4 g_q4[NTOK];
__device__ float4 g_k4[NTOK];
__device__ float4 g_v4[NTOK];
__device__ float4 g_C4[27];    // padded triples, includes 1/sqrt(NQ) scale

// ---------------- complex helpers ----------------
__device__ __forceinline__ float2 cmul(float2 a, float2 b) {
    return make_float2(a.x * b.x - a.y * b.y, a.x * b.y + a.y * b.x);
}
__device__ __forceinline__ float2 cadd(float2 a, float2 b) {
    return make_float2(a.x + b.x, a.y + b.y);
}

// ============================================================
// Parallel setup: build the 81-coefficient multilinear tensor C
// from the fixed circuit unitary. Runs inside qkv block 0.
// ============================================================
__device__ void do_setup(const float* __restrict__ qw) {
    __shared__ float2 U[DIM][DIM];     // U[d][p]: column p = U * e_p
    __shared__ float2 G[8][4];         // per rot gate: G00,G01,G10,G11
    __shared__ float  Mre[DIM][DIM];
    __shared__ float  Ctmp[81];

    int t = threadIdx.x;

    if (t < 8) {
        float a = qw[t * 3 + 0] * 0.5f;
        float b = qw[t * 3 + 1] * 0.5f;
        float c = qw[t * 3 + 2] * 0.5f;
        float ca, sa, cb, sb, cc, sc;
        sincosf(a, &sa, &ca);
        sincosf(b, &sb, &cb);
        sincosf(c, &sc, &cc);
        float2 m00 = make_float2( cb * ca,  sb * sa);
        float2 m01 = make_float2(-sb * ca, -cb * sa);
        float2 m10 = make_float2( sb * ca, -cb * sa);
        float2 m11 = make_float2( cb * ca, -sb * sa);
        float2 ezm = make_float2(cc, -sc);
        float2 ezp = make_float2(cc,  sc);
        G[t][0] = cmul(ezm, m00); G[t][1] = cmul(ezm, m01);
        G[t][2] = cmul(ezp, m10); G[t][3] = cmul(ezp, m11);
    }
    {
        int d = t >> 4, p = t & 15;
        U[d][p] = make_float2(d == p ? 1.f : 0.f, 0.f);
    }
    __syncthreads();

    for (int layer = 0; layer < 2; layer++) {
        #pragma unroll
        for (int w = 0; w < NQ; w++) {
            if (t < 128) {
                int p = t & 15, pr = t >> 4;
                int m = 1 << (3 - w);
                int low = m - 1;
                int i = (pr & low) | ((pr & ~low) << 1);
                int j = i | m;
                int g = layer * 4 + w;
                float2 x0 = U[i][p], x1 = U[j][p];
                U[i][p] = cadd(cmul(G[g][0], x0), cmul(G[g][1], x1));
                U[j][p] = cadd(cmul(G[g][2], x0), cmul(G[g][3], x1));
            }
            __syncthreads();
        }
        {
            int d = t >> 4, p = t & 15;
            int i = d;
            i = (i & 1) ? (i ^ 8) : i;
            i = (i & 2) ? (i ^ 1) : i;
            i = (i & 4) ? (i ^ 2) : i;
            i = (i & 8) ? (i ^ 4) : i;
            float2 val = U[i][p];
            __syncthreads();
            U[d][p] = val;
            __syncthreads();
        }
    }

    {
        int p = t >> 4, q = t & 15;
        float s = 0.f;
        #pragma unroll
        for (int d = 0; d < DIM; d++) {
            float z = (float)(NQ - 2 * __popc(d));
            s += z * (U[d][p].x * U[d][q].x + U[d][p].y * U[d][q].y);
        }
        Mre[p][q] = s;
    }
    __syncthreads();

    if (t < 81) {
        int dg[4];
        dg[0] = t / 27; dg[1] = (t / 9) % 3; dg[2] = (t / 3) % 3; dg[3] = t % 3;
        float acc = 0.f;
        #pragma unroll
        for (int c = 0; c < 16; c++) {
            int p = 0, q = 0;
            float sign = 1.f;
            #pragma unroll
            for (int w = 0; w < 4; w++) {
                int cw = (c >> w) & 1;
                int md = dg[w];
                int pb, qb;
                if (md == 1) { pb = cw; qb = cw ^ 1; }
                else         { pb = cw; qb = cw; if (md == 0 && cw) sign = -sign; }
                p |= pb << (3 - w);
                q |= qb << (3 - w);
            }
            acc += sign * Mre[p][q];
        }
        // (1/2)^4 half-angle * 0.5 softmax scale
        Ctmp[t] = acc * 0.03125f;
    }
    __syncthreads();
    if (t < 27)
        g_C4[t] = make_float4(Ctmp[3 * t], Ctmp[3 * t + 1], Ctmp[3 * t + 2], 0.f);
}

// exp-based tanh: accurate to ~1e-7 relative
__device__ __forceinline__ float ftanh(float x) {
    float e = __expf(2.f * x);
    return __fdividef(e - 1.f, e + 1.f);
}

// ============================================================
// Kernel 1: q/k/v projections, warp-per-token (8 tokens/block).
// Block 0 additionally computes the C tensor.
// ============================================================
__global__ __launch_bounds__(256)
void qkv_kernel(const float* __restrict__ x,
                const float* __restrict__ Wq, const float* __restrict__ bq,
                const float* __restrict__ Wk, const float* __restrict__ bk,
                const float* __restrict__ Wv, const float* __restrict__ bv,
                const float* __restrict__ qw) {
    if (blockIdx.x == 0) do_setup(qw);

    int warp = threadIdx.x >> 5, lane = threadIdx.x & 31;
    int tok = blockIdx.x * 8 + warp;

    float p[12];
    #pragma unroll
    for (int r = 0; r < 12; r++) p[r] = 0.f;

    const float* xr = x + (size_t)tok * EE;
    #pragma unroll 4
    for (int e = lane; e < EE; e += 32) {
        float xv = xr[e];
        float4 wq = __ldg(reinterpret_cast<const float4*>(Wq + e * 4));
        float4 wk = __ldg(reinterpret_cast<const float4*>(Wk + e * 4));
        float4 wv = __ldg(reinterpret_cast<const float4*>(Wv + e * 4));
        p[0] = fmaf(xv, wq.x, p[0]);  p[1] = fmaf(xv, wq.y, p[1]);
        p[2] = fmaf(xv, wq.z, p[2]);  p[3] = fmaf(xv, wq.w, p[3]);
        p[4] = fmaf(xv, wk.x, p[4]);  p[5] = fmaf(xv, wk.y, p[5]);
        p[6] = fmaf(xv, wk.z, p[6]);  p[7] = fmaf(xv, wk.w, p[7]);
        p[8] = fmaf(xv, wv.x, p[8]);  p[9] = fmaf(xv, wv.y, p[9]);
        p[10] = fmaf(xv, wv.z, p[10]); p[11] = fmaf(xv, wv.w, p[11]);
    }
    #pragma unroll
    for (int r = 0; r < 12; r++)
        #pragma unroll
        for (int o = 16; o > 0; o >>= 1)
            p[r] += __shfl_xor_sync(0xFFFFFFFFu, p[r], o);

    if (lane == 0) {
        float* gq = (float*)g_q4;
        float* gk = (float*)g_k4;
        float* gv = (float*)g_v4;
        gq[tok * 4 + 0] = ftanh(p[0] + bq[0]);
        gq[tok * 4 + 1] = ftanh(p[1] + bq[1]);
        gq[tok * 4 + 2] = ftanh(p[2] + bq[2]);
        gq[tok * 4 + 3] = ftanh(p[3] + bq[3]);
        gk[tok * 4 + 0] = ftanh(p[4] + bk[0]);
        gk[tok * 4 + 1] = ftanh(p[5] + bk[1]);
        gk[tok * 4 + 2] = ftanh(p[6] + bk[2]);
        gk[tok * 4 + 3] = ftanh(p[7] + bk[3]);
        gv[tok * 4 + 0] = p[8]  + bv[0];
        gv[tok * 4 + 1] = p[9]  + bv[1];
        gv[tok * 4 + 2] = p[10] + bv[2];
        gv[tok * 4 + 3] = p[11] + bv[3];
    }
}

// ============================================================
// Kernel 2: 4-warps-per-row fused scores + softmax + attend + proj.
// 1024 blocks x 256 threads; block = 2 rows, each row = 4 warps,
// each warp handles 128 j's. No max-subtraction (score in [-2,2]).
// ============================================================
__global__ void __launch_bounds__(256, 8)
main_kernel(const float* __restrict__ Wout, const float* __restrict__ bout,
            float* __restrict__ out, float* __restrict__ attn_out) {
    __shared__ float4 Ksh[SS];
    __shared__ float4 Vsh[SS];
    __shared__ float4 C4[27];
    __shared__ float  WoSh[4 * EE];
    __shared__ float  boSh[EE];
    __shared__ float  red[2][4][5];    // [row_local][warp_seg][{se,sv0..3}]

    int tid = threadIdx.x, lane = tid & 31, warp = tid >> 5;
    int rl   = warp >> 2;              // row within block (0/1)
    int wseg = warp & 3;               // segment of the row (0..3)
    int row  = blockIdx.x * 2 + rl;    // global (b*512 + i)
    int b    = blockIdx.x >> 8;        // 256 blocks per batch

    #pragma unroll
    for (int i = 0; i < 2; i++) {
        int idx = i * 256 + tid;
        Ksh[idx] = g_k4[b * SS + idx];
        Vsh[idx] = g_v4[b * SS + idx];
    }
    #pragma unroll
    for (int i = 0; i < 8; i++) WoSh[i * 256 + tid] = Wout[i * 256 + tid];
    #pragma unroll
    for (int i = 0; i < 2; i++) boSh[i * 256 + tid] = bout[i * 256 + tid];
    if (tid < 27) C4[tid] = g_C4[tid];
    __syncthreads();

    float4 qv = g_q4[row];

    float ej[4];
    float se = 0.f, sv0 = 0.f, sv1 = 0.f, sv2 = 0.f, sv3 = 0.f;

    #pragma unroll
    for (int it = 0; it < 4; it++) {
        int j = wseg * 128 + it * 32 + lane;
        float4 kv = Ksh[j];

        float a0 = ftanh(qv.x + kv.x);
        float a1 = ftanh(qv.y + kv.y);
        float a2 = ftanh(qv.z + kv.z);
        float a3 = ftanh(qv.w + kv.w);

        float c0, s0, c1, s1, c2, s2, c3, s3;
        __sincosf(a0, &s0, &c0);
        __sincosf(a1, &s1, &c1);
        __sincosf(a2, &s2, &c2);
        __sincosf(a3, &s3, &c3);
        float u0[2] = {c0, s0}, u1[2] = {c1, s1}, u2[2] = {c2, s2};

        // score = sum_m C[m] * prod_w u_w[m_w], scale pre-folded into C
        float score = 0.f;
        #pragma unroll
        for (int m0 = 0; m0 < 3; m0++) {
            float t1 = 0.f;
            #pragma unroll
            for (int m1 = 0; m1 < 3; m1++) {
                float t2 = 0.f;
                #pragma unroll
                for (int m2 = 0; m2 < 3; m2++) {
                    float4 c = C4[(m0 * 3 + m1) * 3 + m2];
                    float t3 = fmaf(c.x, c3, fmaf(c.y, s3, c.z));
                    t2 = (m2 == 2) ? (t2 + t3) : fmaf(t3, u2[m2], t2);
                }
                t1 = (m1 == 2) ? (t1 + t2) : fmaf(t2, u1[m1], t1);
            }
            score = (m0 == 2) ? (score + t1) : fmaf(t1, u0[m0], score);
        }

        float e = __expf(score);
        ej[it] = e;
        float4 vv = Vsh[j];
        se  += e;
        sv0 = fmaf(e, vv.x, sv0);
        sv1 = fmaf(e, vv.y, sv1);
        sv2 = fmaf(e, vv.z, sv2);
        sv3 = fmaf(e, vv.w, sv3);
    }

    // warp reduction of 5 values
    #pragma unroll
    for (int o = 16; o > 0; o >>= 1) {
        se  += __shfl_xor_sync(0xFFFFFFFFu, se,  o);
        sv0 += __shfl_xor_sync(0xFFFFFFFFu, sv0, o);
        sv1 += __shfl_xor_sync(0xFFFFFFFFu, sv1, o);
        sv2 += __shfl_xor_sync(0xFFFFFFFFu, sv2, o);
        sv3 += __shfl_xor_sync(0xFFFFFFFFu, sv3, o);
    }
    if (lane == 0) {
        red[rl][wseg][0] = se;
        red[rl][wseg][1] = sv0;
        red[rl][wseg][2] = sv1;
        red[rl][wseg][3] = sv2;
        red[rl][wseg][4] = sv3;
    }
    __syncthreads();

    float tse  = red[rl][0][0] + red[rl][1][0] + red[rl][2][0] + red[rl][3][0];
    float tsv0 = red[rl][0][1] + red[rl][1][1] + red[rl][2][1] + red[rl][3][1];
    float tsv1 = red[rl][0][2] + red[rl][1][2] + red[rl][2][2] + red[rl][3][2];
    float tsv2 = red[rl][0][3] + red[rl][1][3] + red[rl][2][3] + red[rl][3][3];
    float tsv3 = red[rl][0][4] + red[rl][1][4] + red[rl][2][4] + red[rl][3][4];

    float inv = __fdividef(1.f, tse);

    float* arow = attn_out + (size_t)row * SS;
    #pragma unroll
    for (int it = 0; it < 4; it++)
        arow[wseg * 128 + it * 32 + lane] = ej[it] * inv;

    float aw0 = tsv0 * inv, aw1 = tsv1 * inv, aw2 = tsv2 * inv, aw3 = tsv3 * inv;

    float* orow = out + (size_t)row * EE;
    #pragma unroll
    for (int it = 0; it < 4; it++) {
        int e = wseg * 128 + it * 32 + lane;
        float o = boSh[e];
        o = fmaf(aw0, WoSh[e], o);
        o = fmaf(aw1, WoSh[EE + e], o);
        o = fmaf(aw2, WoSh[2 * EE + e], o);
        o = fmaf(aw3, WoSh[3 * EE + e], o);
        orow[e] = o;
    }
}

// ============================================================
extern "C" void kernel_launch(void* const* d_in, const int* in_sizes, int n_in,
                              void* d_out, int out_size) {
    const float* x    = (const float*)d_in[0];
    const float* Wq   = (const float*)d_in[1];
    const float* bq   = (const float*)d_in[2];
    const float* Wk   = (const float*)d_in[3];
    const float* bk   = (const float*)d_in[4];
    const float* Wv   = (const float*)d_in[5];
    const float* bv   = (const float*)d_in[6];
    const float* qw   = (const float*)d_in[7];
    const float* Wout = (const float*)d_in[8];
    const float* bout = (const float*)d_in[9];

    float* out  = (float*)d_out;
    float* attn = out + OUT_ELEMS;

    qkv_kernel<<<NTOK / 8, 256>>>(x, Wq, bq, Wk, bk, Wv, bv, qw);
    main_kernel<<<NTOK / 2, 256>>>(Wout, bout, out, attn);
}

// round 11
// speedup vs baseline: 1.2529x; 1.2529x over previous
#include <cuda_runtime.h>
#include <math.h>

#define NQ 4
#define DIM 16
#define NB 4
#define SS 512
#define EE 512
#define NTOK (NB*SS)           // 2048
#define OUT_ELEMS (NB*SS*EE)   // 1048576

// ---------------- scratch (no device allocation allowed) ----------------
__device__ float4 g_q4[NTOK];
__device__ float4 g_k4[NTOK];
__device__ float4 g_v4[NTOK];
__device__ float4 g_C4[27];    // padded triples, includes 1/sqrt(NQ) scale

// ---------------- complex helpers ----------------
__device__ __forceinline__ float2 cmul(float2 a, float2 b) {
    return make_float2(a.x * b.x - a.y * b.y, a.x * b.y + a.y * b.x);
}
__device__ __forceinline__ float2 cadd(float2 a, float2 b) {
    return make_float2(a.x + b.x, a.y + b.y);
}

// ============================================================
// Parallel setup: build the 81-coefficient multilinear tensor C
// from the fixed circuit unitary. Runs inside qkv block 0.
// ============================================================
__device__ void do_setup(const float* __restrict__ qw) {
    __shared__ float2 U[DIM][DIM];     // U[d][p]: column p = U * e_p
    __shared__ float2 G[8][4];         // per rot gate: G00,G01,G10,G11
    __shared__ float  Mre[DIM][DIM];
    __shared__ float  Ctmp[81];

    int t = threadIdx.x;

    if (t < 8) {
        float a = qw[t * 3 + 0] * 0.5f;
        float b = qw[t * 3 + 1] * 0.5f;
        float c = qw[t * 3 + 2] * 0.5f;
        float ca, sa, cb, sb, cc, sc;
        sincosf(a, &sa, &ca);
        sincosf(b, &sb, &cb);
        sincosf(c, &sc, &cc);
        float2 m00 = make_float2( cb * ca,  sb * sa);
        float2 m01 = make_float2(-sb * ca, -cb * sa);
        float2 m10 = make_float2( sb * ca, -cb * sa);
        float2 m11 = make_float2( cb * ca, -sb * sa);
        float2 ezm = make_float2(cc, -sc);
        float2 ezp = make_float2(cc,  sc);
        G[t][0] = cmul(ezm, m00); G[t][1] = cmul(ezm, m01);
        G[t][2] = cmul(ezp, m10); G[t][3] = cmul(ezp, m11);
    }
    {
        int d = t >> 4, p = t & 15;
        U[d][p] = make_float2(d == p ? 1.f : 0.f, 0.f);
    }
    __syncthreads();

    for (int layer = 0; layer < 2; layer++) {
        #pragma unroll
        for (int w = 0; w < NQ; w++) {
            if (t < 128) {
                int p = t & 15, pr = t >> 4;
                int m = 1 << (3 - w);
                int low = m - 1;
                int i = (pr & low) | ((pr & ~low) << 1);
                int j = i | m;
                int g = layer * 4 + w;
                float2 x0 = U[i][p], x1 = U[j][p];
                U[i][p] = cadd(cmul(G[g][0], x0), cmul(G[g][1], x1));
                U[j][p] = cadd(cmul(G[g][2], x0), cmul(G[g][3], x1));
            }
            __syncthreads();
        }
        {
            int d = t >> 4, p = t & 15;
            int i = d;
            i = (i & 1) ? (i ^ 8) : i;
            i = (i & 2) ? (i ^ 1) : i;
            i = (i & 4) ? (i ^ 2) : i;
            i = (i & 8) ? (i ^ 4) : i;
            float2 val = U[i][p];
            __syncthreads();
            U[d][p] = val;
            __syncthreads();
        }
    }

    {
        int p = t >> 4, q = t & 15;
        float s = 0.f;
        #pragma unroll
        for (int d = 0; d < DIM; d++) {
            float z = (float)(NQ - 2 * __popc(d));
            s += z * (U[d][p].x * U[d][q].x + U[d][p].y * U[d][q].y);
        }
        Mre[p][q] = s;
    }
    __syncthreads();

    if (t < 81) {
        int dg[4];
        dg[0] = t / 27; dg[1] = (t / 9) % 3; dg[2] = (t / 3) % 3; dg[3] = t % 3;
        float acc = 0.f;
        #pragma unroll
        for (int c = 0; c < 16; c++) {
            int p = 0, q = 0;
            float sign = 1.f;
            #pragma unroll
            for (int w = 0; w < 4; w++) {
                int cw = (c >> w) & 1;
                int md = dg[w];
                int pb, qb;
                if (md == 1) { pb = cw; qb = cw ^ 1; }
                else         { pb = cw; qb = cw; if (md == 0 && cw) sign = -sign; }
                p |= pb << (3 - w);
                q |= qb << (3 - w);
            }
            acc += sign * Mre[p][q];
        }
        // (1/2)^4 half-angle * 0.5 softmax scale
        Ctmp[t] = acc * 0.03125f;
    }
    __syncthreads();
    if (t < 27)
        g_C4[t] = make_float4(Ctmp[3 * t], Ctmp[3 * t + 1], Ctmp[3 * t + 2], 0.f);
}

// exp-based tanh: accurate to ~1e-7 relative
__device__ __forceinline__ float ftanh(float x) {
    float e = __expf(2.f * x);
    return __fdividef(e - 1.f, e + 1.f);
}

// ============================================================
// Kernel 1: q/k/v projections, warp-per-token (8 tokens/block).
// Block 0 additionally computes the C tensor.
// ============================================================
__global__ __launch_bounds__(256)
void qkv_kernel(const float* __restrict__ x,
                const float* __restrict__ Wq, const float* __restrict__ bq,
                const float* __restrict__ Wk, const float* __restrict__ bk,
                const float* __restrict__ Wv, const float* __restrict__ bv,
                const float* __restrict__ qw) {
    if (blockIdx.x == 0) do_setup(qw);

    int warp = threadIdx.x >> 5, lane = threadIdx.x & 31;
    int tok = blockIdx.x * 8 + warp;

    float p[12];
    #pragma unroll
    for (int r = 0; r < 12; r++) p[r] = 0.f;

    const float* xr = x + (size_t)tok * EE;
    #pragma unroll 4
    for (int e = lane; e < EE; e += 32) {
        float xv = xr[e];
        float4 wq = __ldg(reinterpret_cast<const float4*>(Wq + e * 4));
        float4 wk = __ldg(reinterpret_cast<const float4*>(Wk + e * 4));
        float4 wv = __ldg(reinterpret_cast<const float4*>(Wv + e * 4));
        p[0] = fmaf(xv, wq.x, p[0]);  p[1] = fmaf(xv, wq.y, p[1]);
        p[2] = fmaf(xv, wq.z, p[2]);  p[3] = fmaf(xv, wq.w, p[3]);
        p[4] = fmaf(xv, wk.x, p[4]);  p[5] = fmaf(xv, wk.y, p[5]);
        p[6] = fmaf(xv, wk.z, p[6]);  p[7] = fmaf(xv, wk.w, p[7]);
        p[8] = fmaf(xv, wv.x, p[8]);  p[9] = fmaf(xv, wv.y, p[9]);
        p[10] = fmaf(xv, wv.z, p[10]); p[11] = fmaf(xv, wv.w, p[11]);
    }
    #pragma unroll
    for (int r = 0; r < 12; r++)
        #pragma unroll
        for (int o = 16; o > 0; o >>= 1)
            p[r] += __shfl_xor_sync(0xFFFFFFFFu, p[r], o);

    if (lane == 0) {
        float* gq = (float*)g_q4;
        float* gk = (float*)g_k4;
        float* gv = (float*)g_v4;
        gq[tok * 4 + 0] = ftanh(p[0] + bq[0]);
        gq[tok * 4 + 1] = ftanh(p[1] + bq[1]);
        gq[tok * 4 + 2] = ftanh(p[2] + bq[2]);
        gq[tok * 4 + 3] = ftanh(p[3] + bq[3]);
        gk[tok * 4 + 0] = ftanh(p[4] + bk[0]);
        gk[tok * 4 + 1] = ftanh(p[5] + bk[1]);
        gk[tok * 4 + 2] = ftanh(p[6] + bk[2]);
        gk[tok * 4 + 3] = ftanh(p[7] + bk[3]);
        gv[tok * 4 + 0] = p[8]  + bv[0];
        gv[tok * 4 + 1] = p[9]  + bv[1];
        gv[tok * 4 + 2] = p[10] + bv[2];
        gv[tok * 4 + 3] = p[11] + bv[3];
    }
}

// ============================================================
// Kernel 2: 4-warps-per-row fused scores + softmax + attend + proj.
// 1024 blocks x 256 threads; block = 2 rows, each row = 4 warps,
// each warp handles 128 j's. No max-subtraction (score in [-2,2]).
// launch_bounds (256,4): 64 regs available -> NO spills (the R10
// (256,8) variant forced 32 regs and spilled to local memory).
// ============================================================
__global__ void __launch_bounds__(256, 4)
main_kernel(const float* __restrict__ Wout, const float* __restrict__ bout,
            float* __restrict__ out, float* __restrict__ attn_out) {
    __shared__ float4 Ksh[SS];
    __shared__ float4 Vsh[SS];
    __shared__ float4 C4[27];
    __shared__ float  WoSh[4 * EE];
    __shared__ float  boSh[EE];
    __shared__ float  red[2][4][5];    // [row_local][warp_seg][{se,sv0..3}]

    int tid = threadIdx.x, lane = tid & 31, warp = tid >> 5;
    int rl   = warp >> 2;              // row within block (0/1)
    int wseg = warp & 3;               // segment of the row (0..3)
    int row  = blockIdx.x * 2 + rl;    // global (b*512 + i)
    int b    = blockIdx.x >> 8;        // 256 blocks per batch

    #pragma unroll
    for (int i = 0; i < 2; i++) {
        int idx = i * 256 + tid;
        Ksh[idx] = g_k4[b * SS + idx];
        Vsh[idx] = g_v4[b * SS + idx];
    }
    #pragma unroll
    for (int i = 0; i < 8; i++) WoSh[i * 256 + tid] = Wout[i * 256 + tid];
    #pragma unroll
    for (int i = 0; i < 2; i++) boSh[i * 256 + tid] = bout[i * 256 + tid];
    if (tid < 27) C4[tid] = g_C4[tid];
    __syncthreads();

    float4 qv = g_q4[row];

    float ej[4];
    float se = 0.f, sv0 = 0.f, sv1 = 0.f, sv2 = 0.f, sv3 = 0.f;

    #pragma unroll
    for (int it = 0; it < 4; it++) {
        int j = wseg * 128 + it * 32 + lane;
        float4 kv = Ksh[j];

        float a0 = ftanh(qv.x + kv.x);
        float a1 = ftanh(qv.y + kv.y);
        float a2 = ftanh(qv.z + kv.z);
        float a3 = ftanh(qv.w + kv.w);

        float c0, s0, c1, s1, c2, s2, c3, s3;
        __sincosf(a0, &s0, &c0);
        __sincosf(a1, &s1, &c1);
        __sincosf(a2, &s2, &c2);
        __sincosf(a3, &s3, &c3);
        float u0[2] = {c0, s0}, u1[2] = {c1, s1}, u2[2] = {c2, s2};

        // score = sum_m C[m] * prod_w u_w[m_w], scale pre-folded into C
        float score = 0.f;
        #pragma unroll
        for (int m0 = 0; m0 < 3; m0++) {
            float t1 = 0.f;
            #pragma unroll
            for (int m1 = 0; m1 < 3; m1++) {
                float t2 = 0.f;
                #pragma unroll
                for (int m2 = 0; m2 < 3; m2++) {
                    float4 c = C4[(m0 * 3 + m1) * 3 + m2];
                    float t3 = fmaf(c.x, c3, fmaf(c.y, s3, c.z));
                    t2 = (m2 == 2) ? (t2 + t3) : fmaf(t3, u2[m2], t2);
                }
                t1 = (m1 == 2) ? (t1 + t2) : fmaf(t2, u1[m1], t1);
            }
            score = (m0 == 2) ? (score + t1) : fmaf(t1, u0[m0], score);
        }

        float e = __expf(score);
        ej[it] = e;
        float4 vv = Vsh[j];
        se  += e;
        sv0 = fmaf(e, vv.x, sv0);
        sv1 = fmaf(e, vv.y, sv1);
        sv2 = fmaf(e, vv.z, sv2);
        sv3 = fmaf(e, vv.w, sv3);
    }

    // warp reduction of 5 values
    #pragma unroll
    for (int o = 16; o > 0; o >>= 1) {
        se  += __shfl_xor_sync(0xFFFFFFFFu, se,  o);
        sv0 += __shfl_xor_sync(0xFFFFFFFFu, sv0, o);
        sv1 += __shfl_xor_sync(0xFFFFFFFFu, sv1, o);
        sv2 += __shfl_xor_sync(0xFFFFFFFFu, sv2, o);
        sv3 += __shfl_xor_sync(0xFFFFFFFFu, sv3, o);
    }
    if (lane == 0) {
        red[rl][wseg][0] = se;
        red[rl][wseg][1] = sv0;
        red[rl][wseg][2] = sv1;
        red[rl][wseg][3] = sv2;
        red[rl][wseg][4] = sv3;
    }
    __syncthreads();

    float tse  = red[rl][0][0] + red[rl][1][0] + red[rl][2][0] + red[rl][3][0];
    float tsv0 = red[rl][0][1] + red[rl][1][1] + red[rl][2][1] + red[rl][3][1];
    float tsv1 = red[rl][0][2] + red[rl][1][2] + red[rl][2][2] + red[rl][3][2];
    float tsv2 = red[rl][0][3] + red[rl][1][3] + red[rl][2][3] + red[rl][3][3];
    float tsv3 = red[rl][0][4] + red[rl][1][4] + red[rl][2][4] + red[rl][3][4];

    float inv = __fdividef(1.f, tse);

    float* arow = attn_out + (size_t)row * SS;
    #pragma unroll
    for (int it = 0; it < 4; it++)
        arow[wseg * 128 + it * 32 + lane] = ej[it] * inv;

    float aw0 = tsv0 * inv, aw1 = tsv1 * inv, aw2 = tsv2 * inv, aw3 = tsv3 * inv;

    float* orow = out + (size_t)row * EE;
    #pragma unroll
    for (int it = 0; it < 4; it++) {
        int e = wseg * 128 + it * 32 + lane;
        float o = boSh[e];
        o = fmaf(aw0, WoSh[e], o);
        o = fmaf(aw1, WoSh[EE + e], o);
        o = fmaf(aw2, WoSh[2 * EE + e], o);
        o = fmaf(aw3, WoSh[3 * EE + e], o);
        orow[e] = o;
    }
}

// ============================================================
extern "C" void kernel_launch(void* const* d_in, const int* in_sizes, int n_in,
                              void* d_out, int out_size) {
    const float* x    = (const float*)d_in[0];
    const float* Wq   = (const float*)d_in[1];
    const float* bq   = (const float*)d_in[2];
    const float* Wk   = (const float*)d_in[3];
    const float* bk   = (const float*)d_in[4];
    const float* Wv   = (const float*)d_in[5];
    const float* bv   = (const float*)d_in[6];
    const float* qw   = (const float*)d_in[7];
    const float* Wout = (const float*)d_in[8];
    const float* bout = (const float*)d_in[9];

    float* out  = (float*)d_out;
    float* attn = out + OUT_ELEMS;

    qkv_kernel<<<NTOK / 8, 256>>>(x, Wq, bq, Wk, bk, Wv, bv, qw);
    main_kernel<<<NTOK / 2, 256>>>(Wout, bout, out, attn);
}

// round 12
// speedup vs baseline: 1.4303x; 1.1416x over previous
#include <cuda_runtime.h>
#include <math.h>

#define NQ 4
#define DIM 16
#define NB 4
#define SS 512
#define EE 512
#define NTOK (NB*SS)           // 2048
#define OUT_ELEMS (NB*SS*EE)   // 1048576

// ---------------- scratch (no device allocation allowed) ----------------
__device__ float4 g_q4[NTOK];
__device__ float4 g_k4[NTOK];
__device__ float4 g_v4[NTOK];
__device__ float4 g_C4[27];    // padded triples, includes 1/sqrt(NQ) scale

// ---------------- complex helpers ----------------
__device__ __forceinline__ float2 cmul(float2 a, float2 b) {
    return make_float2(a.x * b.x - a.y * b.y, a.x * b.y + a.y * b.x);
}
__device__ __forceinline__ float2 cadd(float2 a, float2 b) {
    return make_float2(a.x + b.x, a.y + b.y);
}

// ============================================================
// Parallel setup: build the 81-coefficient multilinear tensor C
// from the fixed circuit unitary. Runs inside qkv block 0.
// ============================================================
__device__ void do_setup(const float* __restrict__ qw) {
    __shared__ float2 U[DIM][DIM];     // U[d][p]: column p = U * e_p
    __shared__ float2 G[8][4];         // per rot gate: G00,G01,G10,G11
    __shared__ float  Mre[DIM][DIM];
    __shared__ float  Ctmp[81];

    int t = threadIdx.x;

    if (t < 8) {
        float a = qw[t * 3 + 0] * 0.5f;
        float b = qw[t * 3 + 1] * 0.5f;
        float c = qw[t * 3 + 2] * 0.5f;
        float ca, sa, cb, sb, cc, sc;
        sincosf(a, &sa, &ca);
        sincosf(b, &sb, &cb);
        sincosf(c, &sc, &cc);
        float2 m00 = make_float2( cb * ca,  sb * sa);
        float2 m01 = make_float2(-sb * ca, -cb * sa);
        float2 m10 = make_float2( sb * ca, -cb * sa);
        float2 m11 = make_float2( cb * ca, -sb * sa);
        float2 ezm = make_float2(cc, -sc);
        float2 ezp = make_float2(cc,  sc);
        G[t][0] = cmul(ezm, m00); G[t][1] = cmul(ezm, m01);
        G[t][2] = cmul(ezp, m10); G[t][3] = cmul(ezp, m11);
    }
    {
        int d = t >> 4, p = t & 15;
        U[d][p] = make_float2(d == p ? 1.f : 0.f, 0.f);
    }
    __syncthreads();

    for (int layer = 0; layer < 2; layer++) {
        #pragma unroll
        for (int w = 0; w < NQ; w++) {
            if (t < 128) {
                int p = t & 15, pr = t >> 4;
                int m = 1 << (3 - w);
                int low = m - 1;
                int i = (pr & low) | ((pr & ~low) << 1);
                int j = i | m;
                int g = layer * 4 + w;
                float2 x0 = U[i][p], x1 = U[j][p];
                U[i][p] = cadd(cmul(G[g][0], x0), cmul(G[g][1], x1));
                U[j][p] = cadd(cmul(G[g][2], x0), cmul(G[g][3], x1));
            }
            __syncthreads();
        }
        {
            int d = t >> 4, p = t & 15;
            int i = d;
            i = (i & 1) ? (i ^ 8) : i;
            i = (i & 2) ? (i ^ 1) : i;
            i = (i & 4) ? (i ^ 2) : i;
            i = (i & 8) ? (i ^ 4) : i;
            float2 val = U[i][p];
            __syncthreads();
            U[d][p] = val;
            __syncthreads();
        }
    }

    {
        int p = t >> 4, q = t & 15;
        float s = 0.f;
        #pragma unroll
        for (int d = 0; d < DIM; d++) {
            float z = (float)(NQ - 2 * __popc(d));
            s += z * (U[d][p].x * U[d][q].x + U[d][p].y * U[d][q].y);
        }
        Mre[p][q] = s;
    }
    __syncthreads();

    if (t < 81) {
        int dg[4];
        dg[0] = t / 27; dg[1] = (t / 9) % 3; dg[2] = (t / 3) % 3; dg[3] = t % 3;
        float acc = 0.f;
        #pragma unroll
        for (int c = 0; c < 16; c++) {
            int p = 0, q = 0;
            float sign = 1.f;
            #pragma unroll
            for (int w = 0; w < 4; w++) {
                int cw = (c >> w) & 1;
                int md = dg[w];
                int pb, qb;
                if (md == 1) { pb = cw; qb = cw ^ 1; }
                else         { pb = cw; qb = cw; if (md == 0 && cw) sign = -sign; }
                p |= pb << (3 - w);
                q |= qb << (3 - w);
            }
            acc += sign * Mre[p][q];
        }
        // (1/2)^4 half-angle * 0.5 softmax scale
        Ctmp[t] = acc * 0.03125f;
    }
    __syncthreads();
    if (t < 27)
        g_C4[t] = make_float4(Ctmp[3 * t], Ctmp[3 * t + 1], Ctmp[3 * t + 2], 0.f);
}

// exp-based tanh: accurate to ~1e-7 relative
__device__ __forceinline__ float ftanh(float x) {
    float e = __expf(2.f * x);
    return __fdividef(e - 1.f, e + 1.f);
}

// ============================================================
// Kernel 1: q/k/v projections, warp-per-token (8 tokens/block).
// Block 0 additionally computes the C tensor.
// ============================================================
__global__ __launch_bounds__(256)
void qkv_kernel(const float* __restrict__ x,
                const float* __restrict__ Wq, const float* __restrict__ bq,
                const float* __restrict__ Wk, const float* __restrict__ bk,
                const float* __restrict__ Wv, const float* __restrict__ bv,
                const float* __restrict__ qw) {
    if (blockIdx.x == 0) do_setup(qw);

    int warp = threadIdx.x >> 5, lane = threadIdx.x & 31;
    int tok = blockIdx.x * 8 + warp;

    float p[12];
    #pragma unroll
    for (int r = 0; r < 12; r++) p[r] = 0.f;

    const float* xr = x + (size_t)tok * EE;
    #pragma unroll 4
    for (int e = lane; e < EE; e += 32) {
        float xv = xr[e];
        float4 wq = __ldg(reinterpret_cast<const float4*>(Wq + e * 4));
        float4 wk = __ldg(reinterpret_cast<const float4*>(Wk + e * 4));
        float4 wv = __ldg(reinterpret_cast<const float4*>(Wv + e * 4));
        p[0] = fmaf(xv, wq.x, p[0]);  p[1] = fmaf(xv, wq.y, p[1]);
        p[2] = fmaf(xv, wq.z, p[2]);  p[3] = fmaf(xv, wq.w, p[3]);
        p[4] = fmaf(xv, wk.x, p[4]);  p[5] = fmaf(xv, wk.y, p[5]);
        p[6] = fmaf(xv, wk.z, p[6]);  p[7] = fmaf(xv, wk.w, p[7]);
        p[8] = fmaf(xv, wv.x, p[8]);  p[9] = fmaf(xv, wv.y, p[9]);
        p[10] = fmaf(xv, wv.z, p[10]); p[11] = fmaf(xv, wv.w, p[11]);
    }
    #pragma unroll
    for (int r = 0; r < 12; r++)
        #pragma unroll
        for (int o = 16; o > 0; o >>= 1)
            p[r] += __shfl_xor_sync(0xFFFFFFFFu, p[r], o);

    if (lane == 0) {
        float* gq = (float*)g_q4;
        float* gk = (float*)g_k4;
        float* gv = (float*)g_v4;
        gq[tok * 4 + 0] = ftanh(p[0] + bq[0]);
        gq[tok * 4 + 1] = ftanh(p[1] + bq[1]);
        gq[tok * 4 + 2] = ftanh(p[2] + bq[2]);
        gq[tok * 4 + 3] = ftanh(p[3] + bq[3]);
        gk[tok * 4 + 0] = ftanh(p[4] + bk[0]);
        gk[tok * 4 + 1] = ftanh(p[5] + bk[1]);
        gk[tok * 4 + 2] = ftanh(p[6] + bk[2]);
        gk[tok * 4 + 3] = ftanh(p[7] + bk[3]);
        gv[tok * 4 + 0] = p[8]  + bv[0];
        gv[tok * 4 + 1] = p[9]  + bv[1];
        gv[tok * 4 + 2] = p[10] + bv[2];
        gv[tok * 4 + 3] = p[11] + bv[3];
    }
}

// ============================================================
// Kernel 2: fused scores + softmax + attend + output projection.
// R4 layout (one block per row, 512 threads, one pair per thread)
// + no max-subtraction (score bounded in [-2,2] analytically)
// + float4 C tensor + pre-folded softmax scale.
// ============================================================
__global__ __launch_bounds__(512)
void main_kernel(const float* __restrict__ Wout, const float* __restrict__ bout,
                 float* __restrict__ out, float* __restrict__ attn_out) {
    __shared__ float4 Ksh[SS];
    __shared__ float4 Vsh[SS];
    __shared__ float4 C4[27];
    __shared__ float  red[16 * 5];
    __shared__ float  fin[5];

    int blk = blockIdx.x;          // b*512 + i
    int b   = blk >> 9;
    int tid = threadIdx.x;

    if (tid < 27) C4[tid] = g_C4[tid];
    Ksh[tid] = g_k4[b * SS + tid];
    Vsh[tid] = g_v4[b * SS + tid];
    float4 qv = g_q4[blk];
    __syncthreads();

    float4 kv = Ksh[tid];

    float a0 = ftanh(qv.x + kv.x);
    float a1 = ftanh(qv.y + kv.y);
    float a2 = ftanh(qv.z + kv.z);
    float a3 = ftanh(qv.w + kv.w);

    float c0, s0, c1, s1, c2, s2, c3, s3;
    __sincosf(a0, &s0, &c0);
    __sincosf(a1, &s1, &c1);
    __sincosf(a2, &s2, &c2);
    __sincosf(a3, &s3, &c3);
    float u0[2] = {c0, s0}, u1[2] = {c1, s1}, u2[2] = {c2, s2};

    // score = sum_m C[m] * prod_w u_w[m_w], scale pre-folded into C
    float score = 0.f;
    #pragma unroll
    for (int m0 = 0; m0 < 3; m0++) {
        float t1 = 0.f;
        #pragma unroll
        for (int m1 = 0; m1 < 3; m1++) {
            float t2 = 0.f;
            #pragma unroll
            for (int m2 = 0; m2 < 3; m2++) {
                float4 c = C4[(m0 * 3 + m1) * 3 + m2];
                float t3 = fmaf(c.x, c3, fmaf(c.y, s3, c.z));
                t2 = (m2 == 2) ? (t2 + t3) : fmaf(t3, u2[m2], t2);
            }
            t1 = (m1 == 2) ? (t1 + t2) : fmaf(t2, u1[m1], t1);
        }
        score = (m0 == 2) ? (score + t1) : fmaf(t1, u0[m0], score);
    }

    float ej = __expf(score);        // no max shift needed: score in [-2,2]
    float4 vv = Vsh[tid];

    // ---- single fused 5-way block reduction: {sum e, sum e*v0..v3} ----
    float vals[5] = { ej, ej * vv.x, ej * vv.y, ej * vv.z, ej * vv.w };
    #pragma unroll
    for (int r = 0; r < 5; r++)
        #pragma unroll
        for (int o = 16; o > 0; o >>= 1)
            vals[r] += __shfl_xor_sync(0xFFFFFFFFu, vals[r], o);

    int lane = tid & 31, warp = tid >> 5;
    if (lane == 0) {
        #pragma unroll
        for (int r = 0; r < 5; r++) red[warp * 5 + r] = vals[r];
    }
    __syncthreads();
    if (tid < 5) {
        float s = 0.f;
        #pragma unroll
        for (int w = 0; w < 16; w++) s += red[w * 5 + tid];
        fin[tid] = s;
    }
    __syncthreads();

    float inv = __fdividef(1.f, fin[0]);
    attn_out[(size_t)blk * SS + tid] = ej * inv;

    float aw0 = fin[1] * inv;
    float aw1 = fin[2] * inv;
    float aw2 = fin[3] * inv;
    float aw3 = fin[4] * inv;

    // out[b,i,e] = sum_w attended[w] * Wout[w,e] + bout[e]   (e = tid)
    float o = bout[tid];
    o = fmaf(aw0, Wout[tid], o);
    o = fmaf(aw1, Wout[EE + tid], o);
    o = fmaf(aw2, Wout[2 * EE + tid], o);
    o = fmaf(aw3, Wout[3 * EE + tid], o);
    out[(size_t)blk * EE + tid] = o;
}

// ============================================================
extern "C" void kernel_launch(void* const* d_in, const int* in_sizes, int n_in,
                              void* d_out, int out_size) {
    const float* x    = (const float*)d_in[0];
    const float* Wq   = (const float*)d_in[1];
    const float* bq   = (const float*)d_in[2];
    const float* Wk   = (const float*)d_in[3];
    const float* bk   = (const float*)d_in[4];
    const float* Wv   = (const float*)d_in[5];
    const float* bv   = (const float*)d_in[6];
    const float* qw   = (const float*)d_in[7];
    const float* Wout = (const float*)d_in[8];
    const float* bout = (const float*)d_in[9];

    float* out  = (float*)d_out;
    float* attn = out + OUT_ELEMS;

    qkv_kernel<<<NTOK / 8, 256>>>(x, Wq, bq, Wk, bk, Wv, bv, qw);
    main_kernel<<<NTOK, 512>>>(Wout, bout, out, attn);
}

// round 15
// speedup vs baseline: 1.5029x; 1.0507x over previous
#include <cuda_runtime.h>
#include <math.h>

#define NQ 4
#define DIM 16
#define NB 4
#define SS 512
#define EE 512
#define NTOK (NB*SS)           // 2048
#define OUT_ELEMS (NB*SS*EE)   // 1048576

// ---------------- scratch (no device allocation allowed) ----------------
__device__ float4 g_q4[NTOK];
__device__ float4 g_k4[NTOK];
__device__ float4 g_v4[NTOK];
__device__ float4 g_C4[27];        // staging: written by setup
__constant__ float4 c_C4[27];      // broadcast path: copied g_C4 -> c_C4 between launches

// ---------------- complex helpers ----------------
__device__ __forceinline__ float2 cmul(float2 a, float2 b) {
    return make_float2(a.x * b.x - a.y * b.y, a.x * b.y + a.y * b.x);
}
__device__ __forceinline__ float2 cadd(float2 a, float2 b) {
    return make_float2(a.x + b.x, a.y + b.y);
}

// ============================================================
// Parallel setup: build the 81-coefficient multilinear tensor C
// from the fixed circuit unitary. Runs inside qkv block 0.
// ============================================================
__device__ void do_setup(const float* __restrict__ qw) {
    __shared__ float2 U[DIM][DIM];     // U[d][p]: column p = U * e_p
    __shared__ float2 G[8][4];         // per rot gate: G00,G01,G10,G11
    __shared__ float  Mre[DIM][DIM];
    __shared__ float  Ctmp[81];

    int t = threadIdx.x;

    if (t < 8) {
        float a = qw[t * 3 + 0] * 0.5f;
        float b = qw[t * 3 + 1] * 0.5f;
        float c = qw[t * 3 + 2] * 0.5f;
        float ca, sa, cb, sb, cc, sc;
        sincosf(a, &sa, &ca);
        sincosf(b, &sb, &cb);
        sincosf(c, &sc, &cc);
        float2 m00 = make_float2( cb * ca,  sb * sa);
        float2 m01 = make_float2(-sb * ca, -cb * sa);
        float2 m10 = make_float2( sb * ca, -cb * sa);
        float2 m11 = make_float2( cb * ca, -sb * sa);
        float2 ezm = make_float2(cc, -sc);
        float2 ezp = make_float2(cc,  sc);
        G[t][0] = cmul(ezm, m00); G[t][1] = cmul(ezm, m01);
        G[t][2] = cmul(ezp, m10); G[t][3] = cmul(ezp, m11);
    }
    {
        int d = t >> 4, p = t & 15;
        U[d][p] = make_float2(d == p ? 1.f : 0.f, 0.f);
    }
    __syncthreads();

    for (int layer = 0; layer < 2; layer++) {
        #pragma unroll
        for (int w = 0; w < NQ; w++) {
            if (t < 128) {
                int p = t & 15, pr = t >> 4;
                int m = 1 << (3 - w);
                int low = m - 1;
                int i = (pr & low) | ((pr & ~low) << 1);
                int j = i | m;
                int g = layer * 4 + w;
                float2 x0 = U[i][p], x1 = U[j][p];
                U[i][p] = cadd(cmul(G[g][0], x0), cmul(G[g][1], x1));
                U[j][p] = cadd(cmul(G[g][2], x0), cmul(G[g][3], x1));
            }
            __syncthreads();
        }
        {
            int d = t >> 4, p = t & 15;
            int i = d;
            i = (i & 1) ? (i ^ 8) : i;
            i = (i & 2) ? (i ^ 1) : i;
            i = (i & 4) ? (i ^ 2) : i;
            i = (i & 8) ? (i ^ 4) : i;
            float2 val = U[i][p];
            __syncthreads();
            U[d][p] = val;
            __syncthreads();
        }
    }

    {
        int p = t >> 4, q = t & 15;
        float s = 0.f;
        #pragma unroll
        for (int d = 0; d < DIM; d++) {
            float z = (float)(NQ - 2 * __popc(d));
            s += z * (U[d][p].x * U[d][q].x + U[d][p].y * U[d][q].y);
        }
        Mre[p][q] = s;
    }
    __syncthreads();

    if (t < 81) {
        int dg[4];
        dg[0] = t / 27; dg[1] = (t / 9) % 3; dg[2] = (t / 3) % 3; dg[3] = t % 3;
        float acc = 0.f;
        #pragma unroll
        for (int c = 0; c < 16; c++) {
            int p = 0, q = 0;
            float sign = 1.f;
            #pragma unroll
            for (int w = 0; w < 4; w++) {
                int cw = (c >> w) & 1;
                int md = dg[w];
                int pb, qb;
                if (md == 1) { pb = cw; qb = cw ^ 1; }
                else         { pb = cw; qb = cw; if (md == 0 && cw) sign = -sign; }
                p |= pb << (3 - w);
                q |= qb << (3 - w);
            }
            acc += sign * Mre[p][q];
        }
        // (1/2)^4 half-angle * 0.5 softmax scale
        Ctmp[t] = acc * 0.03125f;
    }
    __syncthreads();
    if (t < 27)
        g_C4[t] = make_float4(Ctmp[3 * t], Ctmp[3 * t + 1], Ctmp[3 * t + 2], 0.f);
}

// exp-based tanh: accurate to ~1e-7 relative
__device__ __forceinline__ float ftanh(float x) {
    float e = __expf(2.f * x);
    return __fdividef(e - 1.f, e + 1.f);
}

// ============================================================
// Kernel 1: q/k/v projections, warp-per-token (8 tokens/block).
// Block 0 additionally computes the C tensor.
// ============================================================
__global__ __launch_bounds__(256)
void qkv_kernel(const float* __restrict__ x,
                const float* __restrict__ Wq, const float* __restrict__ bq,
                const float* __restrict__ Wk, const float* __restrict__ bk,
                const float* __restrict__ Wv, const float* __restrict__ bv,
                const float* __restrict__ qw) {
    if (blockIdx.x == 0) do_setup(qw);

    int warp = threadIdx.x >> 5, lane = threadIdx.x & 31;
    int tok = blockIdx.x * 8 + warp;

    float p[12];
    #pragma unroll
    for (int r = 0; r < 12; r++) p[r] = 0.f;

    const float* xr = x + (size_t)tok * EE;
    #pragma unroll 4
    for (int e = lane; e < EE; e += 32) {
        float xv = xr[e];
        float4 wq = __ldg(reinterpret_cast<const float4*>(Wq + e * 4));
        float4 wk = __ldg(reinterpret_cast<const float4*>(Wk + e * 4));
        float4 wv = __ldg(reinterpret_cast<const float4*>(Wv + e * 4));
        p[0] = fmaf(xv, wq.x, p[0]);  p[1] = fmaf(xv, wq.y, p[1]);
        p[2] = fmaf(xv, wq.z, p[2]);  p[3] = fmaf(xv, wq.w, p[3]);
        p[4] = fmaf(xv, wk.x, p[4]);  p[5] = fmaf(xv, wk.y, p[5]);
        p[6] = fmaf(xv, wk.z, p[6]);  p[7] = fmaf(xv, wk.w, p[7]);
        p[8] = fmaf(xv, wv.x, p[8]);  p[9] = fmaf(xv, wv.y, p[9]);
        p[10] = fmaf(xv, wv.z, p[10]); p[11] = fmaf(xv, wv.w, p[11]);
    }
    #pragma unroll
    for (int r = 0; r < 12; r++)
        #pragma unroll
        for (int o = 16; o > 0; o >>= 1)
            p[r] += __shfl_xor_sync(0xFFFFFFFFu, p[r], o);

    if (lane == 0) {
        float* gq = (float*)g_q4;
        float* gk = (float*)g_k4;
        float* gv = (float*)g_v4;
        gq[tok * 4 + 0] = ftanh(p[0] + bq[0]);
        gq[tok * 4 + 1] = ftanh(p[1] + bq[1]);
        gq[tok * 4 + 2] = ftanh(p[2] + bq[2]);
        gq[tok * 4 + 3] = ftanh(p[3] + bq[3]);
        gk[tok * 4 + 0] = ftanh(p[4] + bk[0]);
        gk[tok * 4 + 1] = ftanh(p[5] + bk[1]);
        gk[tok * 4 + 2] = ftanh(p[6] + bk[2]);
        gk[tok * 4 + 3] = ftanh(p[7] + bk[3]);
        gv[tok * 4 + 0] = p[8]  + bv[0];
        gv[tok * 4 + 1] = p[9]  + bv[1];
        gv[tok * 4 + 2] = p[10] + bv[2];
        gv[tok * 4 + 3] = p[11] + bv[3];
    }
}

// ============================================================
// Kernel 2: fused scores + softmax + attend + output projection.
// One block per row, 512 threads, one pair per thread.
// C tensor now in __constant__ memory -> LDC/uniform port, not L1.
// No max-subtraction (score analytically bounded in [-2,2]).
// ============================================================
__global__ __launch_bounds__(512)
void main_kernel(const float* __restrict__ Wout, const float* __restrict__ bout,
                 float* __restrict__ out, float* __restrict__ attn_out) {
    __shared__ float4 Ksh[SS];
    __shared__ float4 Vsh[SS];
    __shared__ float  red[16 * 5];
    __shared__ float  fin[5];

    int blk = blockIdx.x;          // b*512 + i
    int b   = blk >> 9;
    int tid = threadIdx.x;

    Ksh[tid] = g_k4[b * SS + tid];
    Vsh[tid] = g_v4[b * SS + tid];
    float4 qv = g_q4[blk];
    __syncthreads();

    float4 kv = Ksh[tid];

    float a0 = ftanh(qv.x + kv.x);
    float a1 = ftanh(qv.y + kv.y);
    float a2 = ftanh(qv.z + kv.z);
    float a3 = ftanh(qv.w + kv.w);

    float c0, s0, c1, s1, c2, s2, c3, s3;
    __sincosf(a0, &s0, &c0);
    __sincosf(a1, &s1, &c1);
    __sincosf(a2, &s2, &c2);
    __sincosf(a3, &s3, &c3);
    float u0[2] = {c0, s0}, u1[2] = {c1, s1}, u2[2] = {c2, s2};

    // score = sum_m C[m] * prod_w u_w[m_w], scale pre-folded into C.
    // C accessed through constant memory with compile-time offsets.
    float score = 0.f;
    #pragma unroll
    for (int m0 = 0; m0 < 3; m0++) {
        float t1 = 0.f;
        #pragma unroll
        for (int m1 = 0; m1 < 3; m1++) {
            float t2 = 0.f;
            #pragma unroll
            for (int m2 = 0; m2 < 3; m2++) {
                float4 c = c_C4[(m0 * 3 + m1) * 3 + m2];
                float t3 = fmaf(c.x, c3, fmaf(c.y, s3, c.z));
                t2 = (m2 == 2) ? (t2 + t3) : fmaf(t3, u2[m2], t2);
            }
            t1 = (m1 == 2) ? (t1 + t2) : fmaf(t2, u1[m1], t1);
        }
        score = (m0 == 2) ? (score + t1) : fmaf(t1, u0[m0], score);
    }

    float ej = __expf(score);        // no max shift needed: score in [-2,2]
    float4 vv = Vsh[tid];

    // ---- single fused 5-way block reduction: {sum e, sum e*v0..v3} ----
    float vals[5] = { ej, ej * vv.x, ej * vv.y, ej * vv.z, ej * vv.w };
    #pragma unroll
    for (int r = 0; r < 5; r++)
        #pragma unroll
        for (int o = 16; o > 0; o >>= 1)
            vals[r] += __shfl_xor_sync(0xFFFFFFFFu, vals[r], o);

    int lane = tid & 31, warp = tid >> 5;
    if (lane == 0) {
        #pragma unroll
        for (int r = 0; r < 5; r++) red[warp * 5 + r] = vals[r];
    }
    __syncthreads();
    if (tid < 5) {
        float s = 0.f;
        #pragma unroll
        for (int w = 0; w < 16; w++) s += red[w * 5 + tid];
        fin[tid] = s;
    }
    __syncthreads();

    float inv = __fdividef(1.f, fin[0]);
    attn_out[(size_t)blk * SS + tid] = ej * inv;

    float aw0 = fin[1] * inv;
    float aw1 = fin[2] * inv;
    float aw2 = fin[3] * inv;
    float aw3 = fin[4] * inv;

    // out[b,i,e] = sum_w attended[w] * Wout[w,e] + bout[e]   (e = tid)
    float o = bout[tid];
    o = fmaf(aw0, Wout[tid], o);
    o = fmaf(aw1, Wout[EE + tid], o);
    o = fmaf(aw2, Wout[2 * EE + tid], o);
    o = fmaf(aw3, Wout[3 * EE + tid], o);
    out[(size_t)blk * EE + tid] = o;
}

// ============================================================
extern "C" void kernel_launch(void* const* d_in, const int* in_sizes, int n_in,
                              void* d_out, int out_size) {
    const float* x    = (const float*)d_in[0];
    const float* Wq   = (const float*)d_in[1];
    const float* bq   = (const float*)d_in[2];
    const float* Wk   = (const float*)d_in[3];
    const float* bk   = (const float*)d_in[4];
    const float* Wv   = (const float*)d_in[5];
    const float* bv   = (const float*)d_in[6];
    const float* qw   = (const float*)d_in[7];
    const float* Wout = (const float*)d_in[8];
    const float* bout = (const float*)d_in[9];

    float* out  = (float*)d_out;
    float* attn = out + OUT_ELEMS;

    qkv_kernel<<<NTOK / 8, 256>>>(x, Wq, bq, Wk, bk, Wv, bv, qw);

    // stage C tensor into constant memory (device-to-device async copy,
    // graph-capturable; ordered after qkv_kernel on the same stream)
    void* c_src = nullptr;
    cudaGetSymbolAddress(&c_src, g_C4);
    cudaMemcpyToSymbolAsync(c_C4, c_src, sizeof(float4) * 27, 0,
                            cudaMemcpyDeviceToDevice);

    main_kernel<<<NTOK, 512>>>(Wout, bout, out, attn);
}

// round 16
// speedup vs baseline: 1.5384x; 1.0236x over previous
#include <cuda_runtime.h>
#include <math.h>

#define NQ 4
#define DIM 16
#define NB 4
#define SS 512
#define EE 512
#define NTOK (NB*SS)           // 2048
#define OUT_ELEMS (NB*SS*EE)   // 1048576

// ---------------- scratch (no device allocation allowed) ----------------
__device__ float4 g_q4[NTOK];      // holds tanh(q) per token
__device__ float4 g_k4[NTOK];      // holds tanh(k) per token
__device__ float4 g_v4[NTOK];
__device__ float4 g_C4[27];        // staging: written by setup
__constant__ float4 c_C4[27];      // broadcast path: copied g_C4 -> c_C4 between launches

// ---------------- complex helpers ----------------
__device__ __forceinline__ float2 cmul(float2 a, float2 b) {
    return make_float2(a.x * b.x - a.y * b.y, a.x * b.y + a.y * b.x);
}
__device__ __forceinline__ float2 cadd(float2 a, float2 b) {
    return make_float2(a.x + b.x, a.y + b.y);
}

// ============================================================
// Parallel setup: build the 81-coefficient multilinear tensor C
// from the fixed circuit unitary. Runs in a DEDICATED block of
// the qkv launch (concurrent with the 256 projection blocks).
// ============================================================
__device__ void do_setup(const float* __restrict__ qw) {
    __shared__ float2 U[DIM][DIM];     // U[d][p]: column p = U * e_p
    __shared__ float2 G[8][4];         // per rot gate: G00,G01,G10,G11
    __shared__ float  Mre[DIM][DIM];
    __shared__ float  Ctmp[81];

    int t = threadIdx.x;

    if (t < 8) {
        float a = qw[t * 3 + 0] * 0.5f;
        float b = qw[t * 3 + 1] * 0.5f;
        float c = qw[t * 3 + 2] * 0.5f;
        float ca, sa, cb, sb, cc, sc;
        sincosf(a, &sa, &ca);
        sincosf(b, &sb, &cb);
        sincosf(c, &sc, &cc);
        float2 m00 = make_float2( cb * ca,  sb * sa);
        float2 m01 = make_float2(-sb * ca, -cb * sa);
        float2 m10 = make_float2( sb * ca, -cb * sa);
        float2 m11 = make_float2( cb * ca, -sb * sa);
        float2 ezm = make_float2(cc, -sc);
        float2 ezp = make_float2(cc,  sc);
        G[t][0] = cmul(ezm, m00); G[t][1] = cmul(ezm, m01);
        G[t][2] = cmul(ezp, m10); G[t][3] = cmul(ezp, m11);
    }
    {
        int d = t >> 4, p = t & 15;
        U[d][p] = make_float2(d == p ? 1.f : 0.f, 0.f);
    }
    __syncthreads();

    for (int layer = 0; layer < 2; layer++) {
        #pragma unroll
        for (int w = 0; w < NQ; w++) {
            if (t < 128) {
                int p = t & 15, pr = t >> 4;
                int m = 1 << (3 - w);
                int low = m - 1;
                int i = (pr & low) | ((pr & ~low) << 1);
                int j = i | m;
                int g = layer * 4 + w;
                float2 x0 = U[i][p], x1 = U[j][p];
                U[i][p] = cadd(cmul(G[g][0], x0), cmul(G[g][1], x1));
                U[j][p] = cadd(cmul(G[g][2], x0), cmul(G[g][3], x1));
            }
            __syncthreads();
        }
        {
            int d = t >> 4, p = t & 15;
            int i = d;
            i = (i & 1) ? (i ^ 8) : i;
            i = (i & 2) ? (i ^ 1) : i;
            i = (i & 4) ? (i ^ 2) : i;
            i = (i & 8) ? (i ^ 4) : i;
            float2 val = U[i][p];
            __syncthreads();
            U[d][p] = val;
            __syncthreads();
        }
    }

    {
        int p = t >> 4, q = t & 15;
        float s = 0.f;
        #pragma unroll
        for (int d = 0; d < DIM; d++) {
            float z = (float)(NQ - 2 * __popc(d));
            s += z * (U[d][p].x * U[d][q].x + U[d][p].y * U[d][q].y);
        }
        Mre[p][q] = s;
    }
    __syncthreads();

    if (t < 81) {
        int dg[4];
        dg[0] = t / 27; dg[1] = (t / 9) % 3; dg[2] = (t / 3) % 3; dg[3] = t % 3;
        float acc = 0.f;
        #pragma unroll
        for (int c = 0; c < 16; c++) {
            int p = 0, q = 0;
            float sign = 1.f;
            #pragma unroll
            for (int w = 0; w < 4; w++) {
                int cw = (c >> w) & 1;
                int md = dg[w];
                int pb, qb;
                if (md == 1) { pb = cw; qb = cw ^ 1; }
                else         { pb = cw; qb = cw; if (md == 0 && cw) sign = -sign; }
                p |= pb << (3 - w);
                q |= qb << (3 - w);
            }
            acc += sign * Mre[p][q];
        }
        // (1/2)^4 half-angle * 0.5 softmax scale
        Ctmp[t] = acc * 0.03125f;
    }
    __syncthreads();
    if (t < 27)
        g_C4[t] = make_float4(Ctmp[3 * t], Ctmp[3 * t + 1], Ctmp[3 * t + 2], 0.f);
}

// exp-based tanh: accurate to ~1e-7 relative
__device__ __forceinline__ float ftanh(float x) {
    float e = __expf(2.f * x);
    return __fdividef(e - 1.f, e + 1.f);
}

// ============================================================
// Kernel 1: q/k/v projections, warp-per-token (8 tokens/block),
// blocks 1..256. Block 0 is DEDICATED to the C-tensor setup.
// Stores tanh(q), tanh(k) (main uses the tanh-addition identity).
// ============================================================
__global__ __launch_bounds__(256)
void qkv_kernel(const float* __restrict__ x,
                const float* __restrict__ Wq, const float* __restrict__ bq,
                const float* __restrict__ Wk, const float* __restrict__ bk,
                const float* __restrict__ Wv, const float* __restrict__ bv,
                const float* __restrict__ qw) {
    if (blockIdx.x == 0) { do_setup(qw); return; }

    int warp = threadIdx.x >> 5, lane = threadIdx.x & 31;
    int tok = (blockIdx.x - 1) * 8 + warp;

    float p[12];
    #pragma unroll
    for (int r = 0; r < 12; r++) p[r] = 0.f;

    const float* xr = x + (size_t)tok * EE;
    #pragma unroll 4
    for (int e = lane; e < EE; e += 32) {
        float xv = xr[e];
        float4 wq = __ldg(reinterpret_cast<const float4*>(Wq + e * 4));
        float4 wk = __ldg(reinterpret_cast<const float4*>(Wk + e * 4));
        float4 wv = __ldg(reinterpret_cast<const float4*>(Wv + e * 4));
        p[0] = fmaf(xv, wq.x, p[0]);  p[1] = fmaf(xv, wq.y, p[1]);
        p[2] = fmaf(xv, wq.z, p[2]);  p[3] = fmaf(xv, wq.w, p[3]);
        p[4] = fmaf(xv, wk.x, p[4]);  p[5] = fmaf(xv, wk.y, p[5]);
        p[6] = fmaf(xv, wk.z, p[6]);  p[7] = fmaf(xv, wk.w, p[7]);
        p[8] = fmaf(xv, wv.x, p[8]);  p[9] = fmaf(xv, wv.y, p[9]);
        p[10] = fmaf(xv, wv.z, p[10]); p[11] = fmaf(xv, wv.w, p[11]);
    }
    #pragma unroll
    for (int r = 0; r < 12; r++)
        #pragma unroll
        for (int o = 16; o > 0; o >>= 1)
            p[r] += __shfl_xor_sync(0xFFFFFFFFu, p[r], o);

    if (lane == 0) {
        float* gq = (float*)g_q4;
        float* gk = (float*)g_k4;
        float* gv = (float*)g_v4;
        // store tanh(q), tanh(k): main uses tanh(u+v) = (tu+tv)/(1+tu*tv)
        gq[tok * 4 + 0] = ftanh(ftanh(p[0] + bq[0]));
        gq[tok * 4 + 1] = ftanh(ftanh(p[1] + bq[1]));
        gq[tok * 4 + 2] = ftanh(ftanh(p[2] + bq[2]));
        gq[tok * 4 + 3] = ftanh(ftanh(p[3] + bq[3]));
        gk[tok * 4 + 0] = ftanh(ftanh(p[4] + bk[0]));
        gk[tok * 4 + 1] = ftanh(ftanh(p[5] + bk[1]));
        gk[tok * 4 + 2] = ftanh(ftanh(p[6] + bk[2]));
        gk[tok * 4 + 3] = ftanh(ftanh(p[7] + bk[3]));
        gv[tok * 4 + 0] = p[8]  + bv[0];
        gv[tok * 4 + 1] = p[9]  + bv[1];
        gv[tok * 4 + 2] = p[10] + bv[2];
        gv[tok * 4 + 3] = p[11] + bv[3];
    }
}

// ============================================================
// Kernel 2: fused scores + softmax + attend + output projection.
// One block per row, 512 threads, one pair per thread.
// C in __constant__; angle via tanh-addition identity (1 RCP vs
// exp+div); no max-subtraction (score bounded in [-2,2]).
// ============================================================
__global__ __launch_bounds__(512)
void main_kernel(const float* __restrict__ Wout, const float* __restrict__ bout,
                 float* __restrict__ out, float* __restrict__ attn_out) {
    __shared__ float4 Ksh[SS];
    __shared__ float4 Vsh[SS];
    __shared__ float  red[16 * 5];
    __shared__ float  fin[5];

    int blk = blockIdx.x;          // b*512 + i
    int b   = blk >> 9;
    int tid = threadIdx.x;

    Ksh[tid] = g_k4[b * SS + tid];
    Vsh[tid] = g_v4[b * SS + tid];
    float4 qv = g_q4[blk];         // tanh(q)
    __syncthreads();

    float4 kv = Ksh[tid];          // tanh(k)

    // a = tanh(q + k) = (tq + tk) / (1 + tq*tk)   (exact identity)
    float a0 = __fdividef(qv.x + kv.x, fmaf(qv.x, kv.x, 1.f));
    float a1 = __fdividef(qv.y + kv.y, fmaf(qv.y, kv.y, 1.f));
    float a2 = __fdividef(qv.z + kv.z, fmaf(qv.z, kv.z, 1.f));
    float a3 = __fdividef(qv.w + kv.w, fmaf(qv.w, kv.w, 1.f));

    float c0, s0, c1, s1, c2, s2, c3, s3;
    __sincosf(a0, &s0, &c0);
    __sincosf(a1, &s1, &c1);
    __sincosf(a2, &s2, &c2);
    __sincosf(a3, &s3, &c3);
    float u0[2] = {c0, s0}, u1[2] = {c1, s1}, u2[2] = {c2, s2};

    // score = sum_m C[m] * prod_w u_w[m_w], scale pre-folded into C.
    float score = 0.f;
    #pragma unroll
    for (int m0 = 0; m0 < 3; m0++) {
        float t1 = 0.f;
        #pragma unroll
        for (int m1 = 0; m1 < 3; m1++) {
            float t2 = 0.f;
            #pragma unroll
            for (int m2 = 0; m2 < 3; m2++) {
                float4 c = c_C4[(m0 * 3 + m1) * 3 + m2];
                float t3 = fmaf(c.x, c3, fmaf(c.y, s3, c.z));
                t2 = (m2 == 2) ? (t2 + t3) : fmaf(t3, u2[m2], t2);
            }
            t1 = (m1 == 2) ? (t1 + t2) : fmaf(t2, u1[m1], t1);
        }
        score = (m0 == 2) ? (score + t1) : fmaf(t1, u0[m0], score);
    }

    float ej = __expf(score);        // no max shift needed: score in [-2,2]
    float4 vv = Vsh[tid];

    // ---- single fused 5-way block reduction: {sum e, sum e*v0..v3} ----
    float vals[5] = { ej, ej * vv.x, ej * vv.y, ej * vv.z, ej * vv.w };
    #pragma unroll
    for (int r = 0; r < 5; r++)
        #pragma unroll
        for (int o = 16; o > 0; o >>= 1)
            vals[r] += __shfl_xor_sync(0xFFFFFFFFu, vals[r], o);

    int lane = tid & 31, warp = tid >> 5;
    if (lane == 0) {
        #pragma unroll
        for (int r = 0; r < 5; r++) red[warp * 5 + r] = vals[r];
    }
    __syncthreads();
    if (tid < 5) {
        float s = 0.f;
        #pragma unroll
        for (int w = 0; w < 16; w++) s += red[w * 5 + tid];
        fin[tid] = s;
    }
    __syncthreads();

    float inv = __fdividef(1.f, fin[0]);
    attn_out[(size_t)blk * SS + tid] = ej * inv;

    float aw0 = fin[1] * inv;
    float aw1 = fin[2] * inv;
    float aw2 = fin[3] * inv;
    float aw3 = fin[4] * inv;

    // out[b,i,e] = sum_w attended[w] * Wout[w,e] + bout[e]   (e = tid)
    float o = bout[tid];
    o = fmaf(aw0, Wout[tid], o);
    o = fmaf(aw1, Wout[EE + tid], o);
    o = fmaf(aw2, Wout[2 * EE + tid], o);
    o = fmaf(aw3, Wout[3 * EE + tid], o);
    out[(size_t)blk * EE + tid] = o;
}

// ============================================================
extern "C" void kernel_launch(void* const* d_in, const int* in_sizes, int n_in,
                              void* d_out, int out_size) {
    const float* x    = (const float*)d_in[0];
    const float* Wq   = (const float*)d_in[1];
    const float* bq   = (const float*)d_in[2];
    const float* Wk   = (const float*)d_in[3];
    const float* bk   = (const float*)d_in[4];
    const float* Wv   = (const float*)d_in[5];
    const float* bv   = (const float*)d_in[6];
    const float* qw   = (const float*)d_in[7];
    const float* Wout = (const float*)d_in[8];
    const float* bout = (const float*)d_in[9];

    float* out  = (float*)d_out;
    float* attn = out + OUT_ELEMS;

    // block 0 = setup (runs concurrently), blocks 1..256 = qkv
    qkv_kernel<<<NTOK / 8 + 1, 256>>>(x, Wq, bq, Wk, bk, Wv, bv, qw);

    // stage C tensor into constant memory (device-to-device async copy,
    // graph-capturable; ordered after qkv_kernel on the same stream)
    void* c_src = nullptr;
    cudaGetSymbolAddress(&c_src, g_C4);
    cudaMemcpyToSymbolAsync(c_C4, c_src, sizeof(float4) * 27, 0,
                            cudaMemcpyDeviceToDevice);

    main_kernel<<<NTOK, 512>>>(Wout, bout, out, attn);
}